// round 4
// baseline (speedup 1.0000x reference)
#include <cuda_runtime.h>

// SymmetricChannel: out[b,l,:] = one_hot(replacement_symbol) if (rand_u < P && argmax(msg)!=0)
//                                else message[b,l,:]
// B=64, L=4096, V=128, P=0.1

#define NROWS (64 * 4096)
#define VOCAB 128

__global__ __launch_bounds__(256) void sym_channel_kernel(
    const float* __restrict__ message,
    const float* __restrict__ rand_u,
    const int*   __restrict__ repl_idx,
    float*       __restrict__ out)
{
    const int row  = blockIdx.x * (blockDim.x >> 5) + (threadIdx.x >> 5);
    if (row >= NROWS) return;
    const int lane = threadIdx.x & 31;

    const float4* mrow = reinterpret_cast<const float4*>(message) + (size_t)row * (VOCAB / 4);
    float4 v = mrow[lane];

    // Local argmax over 4 elements, first-index tiebreak
    const int base = lane * 4;
    float best = v.x; int bidx = base;
    if (v.y > best) { best = v.y; bidx = base + 1; }
    if (v.z > best) { best = v.z; bidx = base + 2; }
    if (v.w > best) { best = v.w; bidx = base + 3; }

    // Warp-wide argmax reduce (prefer larger value; on tie, smaller index = jnp.argmax semantics)
    #pragma unroll
    for (int off = 16; off; off >>= 1) {
        float ov = __shfl_xor_sync(0xffffffffu, best, off);
        int   oi = __shfl_xor_sync(0xffffffffu, bidx, off);
        if (ov > best || (ov == best && oi < bidx)) { best = ov; bidx = oi; }
    }
    // All lanes now hold the row argmax in bidx.

    const float ru = __ldg(rand_u + row);
    const bool combined = (ru < 0.1f) && (bidx != 0);

    float4 o;
    if (combined) {
        // msg != 0 here, so msg_exp == bidx.
        const int r1 = __ldg(repl_idx + row) + 1;
        const int rs = r1 + (r1 >= bidx ? 1 : 0);   // replacement symbol in [1, V-1], != bidx
        o.x = (rs == base    ) ? 1.0f : 0.0f;
        o.y = (rs == base + 1) ? 1.0f : 0.0f;
        o.z = (rs == base + 2) ? 1.0f : 0.0f;
        o.w = (rs == base + 3) ? 1.0f : 0.0f;
    } else {
        o = v;
    }

    reinterpret_cast<float4*>(out)[(size_t)row * (VOCAB / 4) + lane] = o;
}

extern "C" void kernel_launch(void* const* d_in, const int* in_sizes, int n_in,
                              void* d_out, int out_size)
{
    const float* message  = (const float*)d_in[0];
    const float* rand_u   = (const float*)d_in[1];
    const int*   repl_idx = (const int*)  d_in[2];
    float*       out      = (float*)d_out;

    // 8 warps per block, one warp per row
    const int warps_per_block = 8;
    const int blocks = (NROWS + warps_per_block - 1) / warps_per_block;  // 32768
    sym_channel_kernel<<<blocks, warps_per_block * 32>>>(message, rand_u, repl_idx, out);
}

// round 5
// speedup vs baseline: 1.1007x; 1.1007x over previous
#include <cuda_runtime.h>

// SymmetricChannel: out[b,l,:] = one_hot(replacement_symbol) if (rand_u < P && argmax(msg)!=0)
//                                else message[b,l,:]
// B=64, L=4096, V=128, P=0.1
//
// One warp processes ROWS_PER_WARP rows; loads are front-batched for MLP,
// warp argmax uses REDUX.MAX on float bits (positive floats => bit order == value order)
// + ballot + single shuffle, preserving first-index tiebreak.

#define NROWS (64 * 4096)
#define VOCAB 128
#define ROWS_PER_WARP 2

__global__ __launch_bounds__(256) void sym_channel_kernel(
    const float* __restrict__ message,
    const float* __restrict__ rand_u,
    const int*   __restrict__ repl_idx,
    float*       __restrict__ out)
{
    const int warp = blockIdx.x * (blockDim.x >> 5) + (threadIdx.x >> 5);
    const int lane = threadIdx.x & 31;
    const int row0 = warp * ROWS_PER_WARP;
    if (row0 >= NROWS) return;

    const float4* __restrict__ min4  = reinterpret_cast<const float4*>(message);
    float4*       __restrict__ out4  = reinterpret_cast<float4*>(out);

    // ---- front-batch all global loads (MLP) ----
    float4 v[ROWS_PER_WARP];
    float  ru[ROWS_PER_WARP];
    int    ri[ROWS_PER_WARP];
    #pragma unroll
    for (int r = 0; r < ROWS_PER_WARP; r++) {
        v[r]  = min4[(size_t)(row0 + r) * (VOCAB / 4) + lane];
        ru[r] = __ldg(rand_u + row0 + r);     // same addr across warp -> broadcast
        ri[r] = __ldg(repl_idx + row0 + r);
    }

    const int base = lane * 4;

    #pragma unroll
    for (int r = 0; r < ROWS_PER_WARP; r++) {
        // Local argmax over 4 elems, first-index tiebreak (strict >)
        float best = v[r].x; int bidx = base;
        if (v[r].y > best) { best = v[r].y; bidx = base + 1; }
        if (v[r].z > best) { best = v[r].z; bidx = base + 2; }
        if (v[r].w > best) { best = v[r].w; bidx = base + 3; }

        // Warp argmax: REDUX on bits (values are positive => monotone),
        // then lowest lane holding the max has the smallest index range.
        const unsigned bb = __float_as_uint(best);
        const unsigned wm = __reduce_max_sync(0xffffffffu, bb);
        const unsigned ball = __ballot_sync(0xffffffffu, bb == wm);
        const int src = __ffs(ball) - 1;
        const int amax = __shfl_sync(0xffffffffu, bidx, src);

        const bool combined = (ru[r] < 0.1f) && (amax != 0);

        float4 o;
        if (combined) {
            // msg != 0 here, so msg_exp == amax.
            const int r1 = ri[r] + 1;
            const int rs = r1 + (r1 >= amax ? 1 : 0);  // in [1, V-1], != amax
            o.x = (rs == base    ) ? 1.0f : 0.0f;
            o.y = (rs == base + 1) ? 1.0f : 0.0f;
            o.z = (rs == base + 2) ? 1.0f : 0.0f;
            o.w = (rs == base + 3) ? 1.0f : 0.0f;
        } else {
            o = v[r];
        }

        out4[(size_t)(row0 + r) * (VOCAB / 4) + lane] = o;
    }
}

extern "C" void kernel_launch(void* const* d_in, const int* in_sizes, int n_in,
                              void* d_out, int out_size)
{
    const float* message  = (const float*)d_in[0];
    const float* rand_u   = (const float*)d_in[1];
    const int*   repl_idx = (const int*)  d_in[2];
    float*       out      = (float*)d_out;

    const int warps_per_block = 8;
    const int rows_per_block  = warps_per_block * ROWS_PER_WARP;
    const int blocks = (NROWS + rows_per_block - 1) / rows_per_block;  // 16384
    sym_channel_kernel<<<blocks, warps_per_block * 32>>>(message, rand_u, repl_idx, out);
}